// round 1
// baseline (speedup 1.0000x reference)
#include <cuda_runtime.h>

namespace {
constexpr int B = 4, S = 2048, D = 512, H = 8, DK = 64;
}

// Scratch (allocation-free rule: __device__ globals)
__device__ float g_Q[(size_t)B * S * D];
__device__ float g_K[(size_t)B * S * D];
__device__ float g_V[(size_t)B * S * D];
__device__ float g_C[(size_t)B * S * D];
// Fallback home for attention if d_out only holds `output`
__device__ float g_att[(size_t)B * H * S * S];

// ---------------------------------------------------------------------------
// GEMM: Y[M,512] = X[M,512] @ W[512,512]^T + bias   (M = 8192)
// 64x64 tile, 256 threads, 4x4 microtile, BK=16
// ---------------------------------------------------------------------------
__global__ void __launch_bounds__(256) gemm_bias(
    const float* __restrict__ X, const float* __restrict__ W,
    const float* __restrict__ bias, float* __restrict__ Y)
{
    __shared__ float Xs[64][17];
    __shared__ float Ws[64][17];
    const int t  = threadIdx.x;
    const int tx = t & 15, ty = t >> 4;
    const int m0 = blockIdx.y * 64;
    const int n0 = blockIdx.x * 64;
    const int lr = t >> 2;           // 0..63
    const int lc = (t & 3) * 4;      // 0,4,8,12

    float acc[4][4] = {};
    for (int k0 = 0; k0 < 512; k0 += 16) {
        float4 xv = *reinterpret_cast<const float4*>(&X[(size_t)(m0 + lr) * 512 + k0 + lc]);
        float4 wv = *reinterpret_cast<const float4*>(&W[(size_t)(n0 + lr) * 512 + k0 + lc]);
        Xs[lr][lc + 0] = xv.x; Xs[lr][lc + 1] = xv.y; Xs[lr][lc + 2] = xv.z; Xs[lr][lc + 3] = xv.w;
        Ws[lr][lc + 0] = wv.x; Ws[lr][lc + 1] = wv.y; Ws[lr][lc + 2] = wv.z; Ws[lr][lc + 3] = wv.w;
        __syncthreads();
#pragma unroll
        for (int kk = 0; kk < 16; kk++) {
            float a[4], bv[4];
#pragma unroll
            for (int i = 0; i < 4; i++) a[i] = Xs[ty * 4 + i][kk];
#pragma unroll
            for (int j = 0; j < 4; j++) bv[j] = Ws[tx * 4 + j][kk];
#pragma unroll
            for (int i = 0; i < 4; i++)
#pragma unroll
                for (int j = 0; j < 4; j++)
                    acc[i][j] = fmaf(a[i], bv[j], acc[i][j]);
        }
        __syncthreads();
    }
    const int n = n0 + tx * 4;
    const float b0 = bias[n + 0], b1 = bias[n + 1], b2 = bias[n + 2], b3 = bias[n + 3];
#pragma unroll
    for (int i = 0; i < 4; i++) {
        float4 o;
        o.x = acc[i][0] + b0;
        o.y = acc[i][1] + b1;
        o.z = acc[i][2] + b2;
        o.w = acc[i][3] + b3;
        *reinterpret_cast<float4*>(&Y[(size_t)(m0 + ty * 4 + i) * 512 + n]) = o;
    }
}

// ---------------------------------------------------------------------------
// Scores: att[bh, q, k] = (Q . K)/8 + organic(b,h,q), masked
// One 64x64 tile of the S x S score matrix per block; DK=64 fits in one pass.
// ---------------------------------------------------------------------------
__global__ void __launch_bounds__(256) scores_kernel(
    const float* __restrict__ Q, const float* __restrict__ K,
    const int* __restrict__ mask, const float* __restrict__ is_org,
    const float* __restrict__ Worg, const float* __restrict__ borg,
    float* __restrict__ att)
{
    const int bh = blockIdx.z, b = bh >> 3, h = bh & 7;
    const int q0 = blockIdx.y * 64, k0 = blockIdx.x * 64;
    __shared__ float Qs[64][65];
    __shared__ float Ks[64][65];
    const int t = threadIdx.x, tx = t & 15, ty = t >> 4;

    {
        const int c = (t & 15) * 4;
#pragma unroll
        for (int r = 0; r < 4; r++) {
            const int row = (t >> 4) + r * 16;
            float4 qv = *reinterpret_cast<const float4*>(
                &Q[(size_t)(b * S + q0 + row) * D + h * DK + c]);
            float4 kv = *reinterpret_cast<const float4*>(
                &K[(size_t)(b * S + k0 + row) * D + h * DK + c]);
            Qs[row][c + 0] = qv.x; Qs[row][c + 1] = qv.y; Qs[row][c + 2] = qv.z; Qs[row][c + 3] = qv.w;
            Ks[row][c + 0] = kv.x; Ks[row][c + 1] = kv.y; Ks[row][c + 2] = kv.z; Ks[row][c + 3] = kv.w;
        }
    }
    __syncthreads();

    float acc[4][4] = {};
#pragma unroll 16
    for (int d = 0; d < 64; d++) {
        float a[4], bv[4];
#pragma unroll
        for (int i = 0; i < 4; i++) a[i] = Qs[ty * 4 + i][d];
#pragma unroll
        for (int j = 0; j < 4; j++) bv[j] = Ks[tx * 4 + j][d];
#pragma unroll
        for (int i = 0; i < 4; i++)
#pragma unroll
            for (int j = 0; j < 4; j++)
                acc[i][j] = fmaf(a[i], bv[j], acc[i][j]);
    }

    const float worg = Worg[h], bog = borg[h];
    int mj[4];
#pragma unroll
    for (int j = 0; j < 4; j++) mj[j] = mask[b * S + k0 + tx * 4 + j];

#pragma unroll
    for (int i = 0; i < 4; i++) {
        const int q = q0 + ty * 4 + i;
        const float og = is_org[b * S + q] * worg + bog;
        float4 o;
        float v;
        v = acc[i][0] * 0.125f + og; o.x = mj[0] ? v : -1e9f;
        v = acc[i][1] * 0.125f + og; o.y = mj[1] ? v : -1e9f;
        v = acc[i][2] * 0.125f + og; o.z = mj[2] ? v : -1e9f;
        v = acc[i][3] * 0.125f + og; o.w = mj[3] ? v : -1e9f;
        *reinterpret_cast<float4*>(&att[((size_t)bh * S + q) * S + k0 + tx * 4]) = o;
    }
}

// ---------------------------------------------------------------------------
// Row softmax, in place. One block (256 thr) per row of 2048: one read, one write.
// ---------------------------------------------------------------------------
__global__ void __launch_bounds__(256) softmax_kernel(float* __restrict__ att)
{
    float* p = att + (size_t)blockIdx.x * S;
    const int t = threadIdx.x;
    float4 v0 = reinterpret_cast<const float4*>(p)[t * 2 + 0];
    float4 v1 = reinterpret_cast<const float4*>(p)[t * 2 + 1];

    __shared__ float sred[8];

    float m = fmaxf(fmaxf(fmaxf(v0.x, v0.y), fmaxf(v0.z, v0.w)),
                    fmaxf(fmaxf(v1.x, v1.y), fmaxf(v1.z, v1.w)));
#pragma unroll
    for (int o = 16; o; o >>= 1) m = fmaxf(m, __shfl_xor_sync(0xffffffffu, m, o));
    if ((t & 31) == 0) sred[t >> 5] = m;
    __syncthreads();
    float mm = sred[0];
#pragma unroll
    for (int i = 1; i < 8; i++) mm = fmaxf(mm, sred[i]);
    __syncthreads();

    v0.x = expf(v0.x - mm); v0.y = expf(v0.y - mm);
    v0.z = expf(v0.z - mm); v0.w = expf(v0.w - mm);
    v1.x = expf(v1.x - mm); v1.y = expf(v1.y - mm);
    v1.z = expf(v1.z - mm); v1.w = expf(v1.w - mm);

    float s = v0.x + v0.y + v0.z + v0.w + v1.x + v1.y + v1.z + v1.w;
#pragma unroll
    for (int o = 16; o; o >>= 1) s += __shfl_xor_sync(0xffffffffu, s, o);
    if ((t & 31) == 0) sred[t >> 5] = s;
    __syncthreads();
    float ss = sred[0];
#pragma unroll
    for (int i = 1; i < 8; i++) ss += sred[i];
    const float inv = 1.0f / ss;

    v0.x *= inv; v0.y *= inv; v0.z *= inv; v0.w *= inv;
    v1.x *= inv; v1.y *= inv; v1.z *= inv; v1.w *= inv;
    reinterpret_cast<float4*>(p)[t * 2 + 0] = v0;
    reinterpret_cast<float4*>(p)[t * 2 + 1] = v1;
}

// ---------------------------------------------------------------------------
// AV: C[b*S+q, h*64+d] = sum_k att[bh,q,k] * V[b*S+k, h*64+d]
// 64(q) x 64(dk) per block, BK=32 over k.
// ---------------------------------------------------------------------------
__global__ void __launch_bounds__(256) av_kernel(
    const float* __restrict__ att, const float* __restrict__ V,
    float* __restrict__ C)
{
    const int bh = blockIdx.y, b = bh >> 3, h = bh & 7;
    const int q0 = blockIdx.x * 64;
    __shared__ float As[64][36];
    __shared__ float Vs[32][68];
    const int t = threadIdx.x, tx = t & 15, ty = t >> 4;
    const size_t attbase = ((size_t)bh * S + q0) * S;

    float acc[4][4] = {};
    for (int k0 = 0; k0 < S; k0 += 32) {
        {
            const int row = t >> 2, c = (t & 3) * 8;
            const float* src = &att[attbase + (size_t)row * S + k0 + c];
            float4 a0 = reinterpret_cast<const float4*>(src)[0];
            float4 a1 = reinterpret_cast<const float4*>(src)[1];
            *reinterpret_cast<float4*>(&As[row][c])     = a0;
            *reinterpret_cast<float4*>(&As[row][c + 4]) = a1;
        }
        {
            const int row = t >> 3, c = (t & 7) * 8;
            const float* src = &V[(size_t)(b * S + k0 + row) * D + h * DK + c];
            float4 w0 = reinterpret_cast<const float4*>(src)[0];
            float4 w1 = reinterpret_cast<const float4*>(src)[1];
            *reinterpret_cast<float4*>(&Vs[row][c])     = w0;
            *reinterpret_cast<float4*>(&Vs[row][c + 4]) = w1;
        }
        __syncthreads();
#pragma unroll
        for (int kk = 0; kk < 32; kk++) {
            float a[4], vv[4];
#pragma unroll
            for (int i = 0; i < 4; i++) a[i] = As[ty * 4 + i][kk];
#pragma unroll
            for (int j = 0; j < 4; j++) vv[j] = Vs[kk][tx * 4 + j];
#pragma unroll
            for (int i = 0; i < 4; i++)
#pragma unroll
                for (int j = 0; j < 4; j++)
                    acc[i][j] = fmaf(a[i], vv[j], acc[i][j]);
        }
        __syncthreads();
    }
#pragma unroll
    for (int i = 0; i < 4; i++) {
        float4 o;
        o.x = acc[i][0]; o.y = acc[i][1]; o.z = acc[i][2]; o.w = acc[i][3];
        *reinterpret_cast<float4*>(
            &C[(size_t)(b * S + q0 + ty * 4 + i) * D + h * DK + tx * 4]) = o;
    }
}

// ---------------------------------------------------------------------------
extern "C" void kernel_launch(void* const* d_in, const int* in_sizes, int n_in,
                              void* d_out, int out_size)
{
    const float* query = (const float*)d_in[0];
    const float* key   = (const float*)d_in[1];
    const float* value = (const float*)d_in[2];
    const int*   mask  = (const int*)d_in[3];
    const float* isog  = (const float*)d_in[4];
    const float* Wq    = (const float*)d_in[5];
    const float* bq    = (const float*)d_in[6];
    const float* Wk    = (const float*)d_in[7];
    const float* bk    = (const float*)d_in[8];
    const float* Wv    = (const float*)d_in[9];
    const float* bv    = (const float*)d_in[10];
    const float* Wo    = (const float*)d_in[11];
    const float* bo    = (const float*)d_in[12];
    const float* Worg  = (const float*)d_in[13];
    const float* borg  = (const float*)d_in[14];

    float* out = (float*)d_out;

    float *qbuf, *kbuf, *vbuf, *cbuf;
    cudaGetSymbolAddress((void**)&qbuf, g_Q);
    cudaGetSymbolAddress((void**)&kbuf, g_K);
    cudaGetSymbolAddress((void**)&vbuf, g_V);
    cudaGetSymbolAddress((void**)&cbuf, g_C);

    const long long OUT_MAIN = (long long)B * S * D;          // 4,194,304
    const long long ATT_SZ   = (long long)B * H * S * S;      // 134,217,728
    float* att;
    if ((long long)out_size >= OUT_MAIN + ATT_SZ) {
        att = out + OUT_MAIN;                  // tuple output: (output, attention)
    } else {
        cudaGetSymbolAddress((void**)&att, g_att);   // attention not checked; scratch
    }

    dim3 gg(8, 128);      // N/64 x M/64
    gemm_bias<<<gg, 256>>>(query, Wq, bq, qbuf);
    gemm_bias<<<gg, 256>>>(key,   Wk, bk, kbuf);
    gemm_bias<<<gg, 256>>>(value, Wv, bv, vbuf);

    dim3 gs(S / 64, S / 64, B * H);
    scores_kernel<<<gs, 256>>>(qbuf, kbuf, mask, isog, Worg, borg, att);

    softmax_kernel<<<B * H * S, 256>>>(att);

    dim3 ga(S / 64, B * H);
    av_kernel<<<ga, 256>>>(att, vbuf, cbuf);

    gemm_bias<<<gg, 256>>>(cbuf, Wo, bo, out);
}

// round 3
// speedup vs baseline: 1.3083x; 1.3083x over previous
#include <cuda_runtime.h>
#include <cstdint>

namespace {
constexpr int B = 4, S = 2048, D = 512, H = 8, DK = 64;
}

// Scratch (allocation-free rule: __device__ globals)
__device__ float g_Q[(size_t)B * S * D];
__device__ float g_K[(size_t)B * S * D];
__device__ float g_V[(size_t)B * S * D];
__device__ float g_C[(size_t)B * S * D];
__device__ float g_att[(size_t)B * H * S * S];

// ============================================================================
// Warp-level tf32 MMA helpers (portable PTX — works on compute_103)
// ============================================================================
__device__ __forceinline__ uint32_t f2tf32(float x) {
    uint32_t u;
    asm("cvt.rna.tf32.f32 %0, %1;" : "=r"(u) : "f"(x));
    return u;
}
__device__ __forceinline__ void split_tf32(float x, uint32_t& hi, uint32_t& lo) {
    hi = f2tf32(x);
    lo = f2tf32(x - __uint_as_float(hi));
}
__device__ __forceinline__ void mma_tf32(float c[4], const uint32_t a[4], const uint32_t b[2]) {
    asm volatile(
        "mma.sync.aligned.m16n8k8.row.col.f32.tf32.tf32.f32 "
        "{%0,%1,%2,%3}, {%4,%5,%6,%7}, {%8,%9}, {%0,%1,%2,%3};"
        : "+f"(c[0]), "+f"(c[1]), "+f"(c[2]), "+f"(c[3])
        : "r"(a[0]), "r"(a[1]), "r"(a[2]), "r"(a[3]), "r"(b[0]), "r"(b[1]));
}

// ============================================================================
// Scores via mma.sync tf32 (3xTF32): att[bh,q,k] = (Q.K)/8 + organic, masked
// CTA: 128(q) x 128(k) tile, 256 threads = 8 warps (2m x 4n), warp 64x32.
// smem: Qs[128][68], Ks[128][68]  (both [row][dk], K tile is B col-major)
// ============================================================================
namespace {
constexpr int SC_STRIDE = 68;
constexpr int SC_QS = 0;
constexpr int SC_KS = 128 * SC_STRIDE;                 // floats
constexpr int SMEM_SCORES = 2 * 128 * SC_STRIDE * 4;   // 69,632 bytes
}

__global__ void __launch_bounds__(256) scores_mma(
    const float* __restrict__ Q, const float* __restrict__ K,
    const int* __restrict__ mask, const float* __restrict__ is_org,
    const float* __restrict__ Worg, const float* __restrict__ borg,
    float* __restrict__ att)
{
    extern __shared__ float sm[];
    float* Qs = sm + SC_QS;   // [128][68]
    float* Ks = sm + SC_KS;   // [128][68]

    const int t = threadIdx.x, lane = t & 31, wid = t >> 5;
    const int g = lane >> 2, tig = lane & 3;
    const int wm = wid & 1, wn = wid >> 1;          // warp tile: (wm*64, wn*32)
    const int bh = blockIdx.z, b = bh >> 3, h = bh & 7;
    const int q0 = blockIdx.y * 128, k0g = blockIdx.x * 128;

    const float* Qg = Q + ((size_t)(b * S + q0)) * D + h * DK;
    const float* Kg = K + ((size_t)(b * S + k0g)) * D + h * DK;

#pragma unroll
    for (int i = t; i < 2048; i += 256) {
        const int row = i >> 4, c4 = (i & 15) * 4;
        float4 qv = *reinterpret_cast<const float4*>(Qg + (size_t)row * D + c4);
        float4 kv = *reinterpret_cast<const float4*>(Kg + (size_t)row * D + c4);
        *reinterpret_cast<float4*>(&Qs[row * SC_STRIDE + c4]) = qv;
        *reinterpret_cast<float4*>(&Ks[row * SC_STRIDE + c4]) = kv;
    }
    __syncthreads();

    float acc[4][4][4] = {};   // [m-tile][n-tile][frag]

#pragma unroll
    for (int ks = 0; ks < 8; ks++) {
        const int kk = ks * 8;
        uint32_t ahi[4][4], alo[4][4];
#pragma unroll
        for (int i = 0; i < 4; i++) {
            const int r0 = (wm * 64 + i * 16 + g) * SC_STRIDE;
            const int r1 = r0 + 8 * SC_STRIDE;
            split_tf32(Qs[r0 + kk + tig],     ahi[i][0], alo[i][0]);
            split_tf32(Qs[r1 + kk + tig],     ahi[i][1], alo[i][1]);
            split_tf32(Qs[r0 + kk + tig + 4], ahi[i][2], alo[i][2]);
            split_tf32(Qs[r1 + kk + tig + 4], ahi[i][3], alo[i][3]);
        }
#pragma unroll
        for (int j = 0; j < 4; j++) {
            const int nr = (wn * 32 + j * 8 + g) * SC_STRIDE;
            uint32_t bhi[2], blo[2];
            split_tf32(Ks[nr + kk + tig],     bhi[0], blo[0]);
            split_tf32(Ks[nr + kk + tig + 4], bhi[1], blo[1]);
#pragma unroll
            for (int i = 0; i < 4; i++) {
                mma_tf32(acc[i][j], ahi[i], bhi);
                mma_tf32(acc[i][j], alo[i], bhi);
                mma_tf32(acc[i][j], ahi[i], blo);
            }
        }
    }

    // Epilogue: scale + organic + mask -> global (float2 per c-pair)
    const float worg = __ldg(Worg + h), bog = __ldg(borg + h);
    float og[4][2];
#pragma unroll
    for (int i = 0; i < 4; i++) {
#pragma unroll
        for (int hh = 0; hh < 2; hh++) {
            const int row = q0 + wm * 64 + i * 16 + g + hh * 8;
            og[i][hh] = __ldg(is_org + b * S + row) * worg + bog;
        }
    }
    int2 mj[4];
#pragma unroll
    for (int j = 0; j < 4; j++) {
        const int col = k0g + wn * 32 + j * 8 + 2 * tig;
        mj[j] = *reinterpret_cast<const int2*>(mask + b * S + col);
    }

#pragma unroll
    for (int i = 0; i < 4; i++) {
        const int row0 = q0 + wm * 64 + i * 16 + g;
#pragma unroll
        for (int j = 0; j < 4; j++) {
            const int col = k0g + wn * 32 + j * 8 + 2 * tig;
            float2 o;
            float v;
            v = acc[i][j][0] * 0.125f + og[i][0]; o.x = mj[j].x ? v : -1e9f;
            v = acc[i][j][1] * 0.125f + og[i][0]; o.y = mj[j].y ? v : -1e9f;
            *reinterpret_cast<float2*>(&att[((size_t)bh * S + row0) * S + col]) = o;
            v = acc[i][j][2] * 0.125f + og[i][1]; o.x = mj[j].x ? v : -1e9f;
            v = acc[i][j][3] * 0.125f + og[i][1]; o.y = mj[j].y ? v : -1e9f;
            *reinterpret_cast<float2*>(&att[((size_t)bh * S + row0 + 8) * S + col]) = o;
        }
    }
}

// ============================================================================
// AV via mma.sync tf32 (3xTF32): C[q, h*64+d] = sum_k att[bh,q,k] * V[k, h*64+d]
// CTA: 128(q) x 64(d), 256 threads = 8 warps (4m x 2n), warp 32x32, KC=64.
// smem: As[128][68] ([q][k]), Vs[64][68] ([d][k] — transposed for B frags)
// ============================================================================
namespace {
constexpr int AV_STRIDE = 68;
constexpr int AV_AS = 0;
constexpr int AV_VS = 128 * AV_STRIDE;
constexpr int SMEM_AV = (128 + 64) * AV_STRIDE * 4;    // 52,224 bytes
}

__global__ void __launch_bounds__(256) av_mma(
    const float* __restrict__ att, const float* __restrict__ V,
    float* __restrict__ C)
{
    extern __shared__ float sm[];
    float* As = sm + AV_AS;   // [128][68]
    float* Vs = sm + AV_VS;   // [64][68]  (Vs[d][k])

    const int t = threadIdx.x, lane = t & 31, wid = t >> 5;
    const int g = lane >> 2, tig = lane & 3;
    const int wm = wid & 3, wn = wid >> 2;          // warp tile: (wm*32, wn*32)
    const int bh = blockIdx.y, b = bh >> 3, h = bh & 7;
    const int q0 = blockIdx.x * 128;

    float acc[2][4][4] = {};

    for (int kc = 0; kc < S; kc += 64) {
        // att tile [128 q][64 k]
#pragma unroll
        for (int i = t; i < 2048; i += 256) {
            const int row = i >> 4, c4 = (i & 15) * 4;
            float4 av = *reinterpret_cast<const float4*>(
                &att[((size_t)bh * S + q0 + row) * S + kc + c4]);
            *reinterpret_cast<float4*>(&As[row * AV_STRIDE + c4]) = av;
        }
        // V tile transposed: Vs[d][k] = V[(b*S+kc+k)*D + h*64 + d]
#pragma unroll
        for (int i = t; i < 1024; i += 256) {
            const int k = i & 63, d4 = (i >> 6) * 4;
            float4 vv = *reinterpret_cast<const float4*>(
                &V[(size_t)(b * S + kc + k) * D + h * DK + d4]);
            Vs[(d4 + 0) * AV_STRIDE + k] = vv.x;
            Vs[(d4 + 1) * AV_STRIDE + k] = vv.y;
            Vs[(d4 + 2) * AV_STRIDE + k] = vv.z;
            Vs[(d4 + 3) * AV_STRIDE + k] = vv.w;
        }
        __syncthreads();

#pragma unroll
        for (int ks = 0; ks < 8; ks++) {
            const int kk = ks * 8;
            uint32_t ahi[2][4], alo[2][4];
#pragma unroll
            for (int i = 0; i < 2; i++) {
                const int r0 = (wm * 32 + i * 16 + g) * AV_STRIDE;
                const int r1 = r0 + 8 * AV_STRIDE;
                split_tf32(As[r0 + kk + tig],     ahi[i][0], alo[i][0]);
                split_tf32(As[r1 + kk + tig],     ahi[i][1], alo[i][1]);
                split_tf32(As[r0 + kk + tig + 4], ahi[i][2], alo[i][2]);
                split_tf32(As[r1 + kk + tig + 4], ahi[i][3], alo[i][3]);
            }
#pragma unroll
            for (int j = 0; j < 4; j++) {
                const int nr = (wn * 32 + j * 8 + g) * AV_STRIDE;
                uint32_t bhi[2], blo[2];
                split_tf32(Vs[nr + kk + tig],     bhi[0], blo[0]);
                split_tf32(Vs[nr + kk + tig + 4], bhi[1], blo[1]);
#pragma unroll
                for (int i = 0; i < 2; i++) {
                    mma_tf32(acc[i][j], ahi[i], bhi);
                    mma_tf32(acc[i][j], alo[i], bhi);
                    mma_tf32(acc[i][j], ahi[i], blo);
                }
            }
        }
        __syncthreads();
    }

#pragma unroll
    for (int i = 0; i < 2; i++) {
        const int row0 = q0 + wm * 32 + i * 16 + g;
#pragma unroll
        for (int j = 0; j < 4; j++) {
            const int col = h * DK + wn * 32 + j * 8 + 2 * tig;
            float2 o;
            o.x = acc[i][j][0]; o.y = acc[i][j][1];
            *reinterpret_cast<float2*>(&C[(size_t)(b * S + row0) * D + col]) = o;
            o.x = acc[i][j][2]; o.y = acc[i][j][3];
            *reinterpret_cast<float2*>(&C[(size_t)(b * S + row0 + 8) * D + col]) = o;
        }
    }
}

// ---------------------------------------------------------------------------
// GEMM: Y[M,512] = X[M,512] @ W[512,512]^T + bias   (M = 8192)  [FFMA]
// ---------------------------------------------------------------------------
__global__ void __launch_bounds__(256) gemm_bias(
    const float* __restrict__ X, const float* __restrict__ W,
    const float* __restrict__ bias, float* __restrict__ Y)
{
    __shared__ float Xs[64][17];
    __shared__ float Ws[64][17];
    const int t  = threadIdx.x;
    const int tx = t & 15, ty = t >> 4;
    const int m0 = blockIdx.y * 64;
    const int n0 = blockIdx.x * 64;
    const int lr = t >> 2;
    const int lc = (t & 3) * 4;

    float acc[4][4] = {};
    for (int k0 = 0; k0 < 512; k0 += 16) {
        float4 xv = *reinterpret_cast<const float4*>(&X[(size_t)(m0 + lr) * 512 + k0 + lc]);
        float4 wv = *reinterpret_cast<const float4*>(&W[(size_t)(n0 + lr) * 512 + k0 + lc]);
        Xs[lr][lc + 0] = xv.x; Xs[lr][lc + 1] = xv.y; Xs[lr][lc + 2] = xv.z; Xs[lr][lc + 3] = xv.w;
        Ws[lr][lc + 0] = wv.x; Ws[lr][lc + 1] = wv.y; Ws[lr][lc + 2] = wv.z; Ws[lr][lc + 3] = wv.w;
        __syncthreads();
#pragma unroll
        for (int kk = 0; kk < 16; kk++) {
            float a[4], bv[4];
#pragma unroll
            for (int i = 0; i < 4; i++) a[i] = Xs[ty * 4 + i][kk];
#pragma unroll
            for (int j = 0; j < 4; j++) bv[j] = Ws[tx * 4 + j][kk];
#pragma unroll
            for (int i = 0; i < 4; i++)
#pragma unroll
                for (int j = 0; j < 4; j++)
                    acc[i][j] = fmaf(a[i], bv[j], acc[i][j]);
        }
        __syncthreads();
    }
    const int n = n0 + tx * 4;
    const float b0 = bias[n + 0], b1 = bias[n + 1], b2 = bias[n + 2], b3 = bias[n + 3];
#pragma unroll
    for (int i = 0; i < 4; i++) {
        float4 o;
        o.x = acc[i][0] + b0;
        o.y = acc[i][1] + b1;
        o.z = acc[i][2] + b2;
        o.w = acc[i][3] + b3;
        *reinterpret_cast<float4*>(&Y[(size_t)(m0 + ty * 4 + i) * 512 + n]) = o;
    }
}

// ---------------------------------------------------------------------------
// Row softmax, in place
// ---------------------------------------------------------------------------
__global__ void __launch_bounds__(256) softmax_kernel(float* __restrict__ att)
{
    float* p = att + (size_t)blockIdx.x * S;
    const int t = threadIdx.x;
    float4 v0 = reinterpret_cast<const float4*>(p)[t * 2 + 0];
    float4 v1 = reinterpret_cast<const float4*>(p)[t * 2 + 1];

    __shared__ float sred[8];

    float m = fmaxf(fmaxf(fmaxf(v0.x, v0.y), fmaxf(v0.z, v0.w)),
                    fmaxf(fmaxf(v1.x, v1.y), fmaxf(v1.z, v1.w)));
#pragma unroll
    for (int o = 16; o; o >>= 1) m = fmaxf(m, __shfl_xor_sync(0xffffffffu, m, o));
    if ((t & 31) == 0) sred[t >> 5] = m;
    __syncthreads();
    float mm = sred[0];
#pragma unroll
    for (int i = 1; i < 8; i++) mm = fmaxf(mm, sred[i]);
    __syncthreads();

    v0.x = expf(v0.x - mm); v0.y = expf(v0.y - mm);
    v0.z = expf(v0.z - mm); v0.w = expf(v0.w - mm);
    v1.x = expf(v1.x - mm); v1.y = expf(v1.y - mm);
    v1.z = expf(v1.z - mm); v1.w = expf(v1.w - mm);

    float s = v0.x + v0.y + v0.z + v0.w + v1.x + v1.y + v1.z + v1.w;
#pragma unroll
    for (int o = 16; o; o >>= 1) s += __shfl_xor_sync(0xffffffffu, s, o);
    if ((t & 31) == 0) sred[t >> 5] = s;
    __syncthreads();
    float ss = sred[0];
#pragma unroll
    for (int i = 1; i < 8; i++) ss += sred[i];
    const float inv = 1.0f / ss;

    v0.x *= inv; v0.y *= inv; v0.z *= inv; v0.w *= inv;
    v1.x *= inv; v1.y *= inv; v1.z *= inv; v1.w *= inv;
    reinterpret_cast<float4*>(p)[t * 2 + 0] = v0;
    reinterpret_cast<float4*>(p)[t * 2 + 1] = v1;
}

// ---------------------------------------------------------------------------
extern "C" void kernel_launch(void* const* d_in, const int* in_sizes, int n_in,
                              void* d_out, int out_size)
{
    const float* query = (const float*)d_in[0];
    const float* key   = (const float*)d_in[1];
    const float* value = (const float*)d_in[2];
    const int*   mask  = (const int*)d_in[3];
    const float* isog  = (const float*)d_in[4];
    const float* Wq    = (const float*)d_in[5];
    const float* bq    = (const float*)d_in[6];
    const float* Wk    = (const float*)d_in[7];
    const float* bk    = (const float*)d_in[8];
    const float* Wv    = (const float*)d_in[9];
    const float* bv    = (const float*)d_in[10];
    const float* Wo    = (const float*)d_in[11];
    const float* bo    = (const float*)d_in[12];
    const float* Worg  = (const float*)d_in[13];
    const float* borg  = (const float*)d_in[14];

    float* out = (float*)d_out;

    float *qbuf, *kbuf, *vbuf, *cbuf;
    cudaGetSymbolAddress((void**)&qbuf, g_Q);
    cudaGetSymbolAddress((void**)&kbuf, g_K);
    cudaGetSymbolAddress((void**)&vbuf, g_V);
    cudaGetSymbolAddress((void**)&cbuf, g_C);

    const long long OUT_MAIN = (long long)B * S * D;
    const long long ATT_SZ   = (long long)B * H * S * S;
    float* att;
    if ((long long)out_size >= OUT_MAIN + ATT_SZ) {
        att = out + OUT_MAIN;
    } else {
        cudaGetSymbolAddress((void**)&att, g_att);
    }

    static bool attr_done = false;
    if (!attr_done) {
        cudaFuncSetAttribute(scores_mma, cudaFuncAttributeMaxDynamicSharedMemorySize, SMEM_SCORES);
        cudaFuncSetAttribute(av_mma, cudaFuncAttributeMaxDynamicSharedMemorySize, SMEM_AV);
        attr_done = true;
    }

    dim3 gg(8, 128);
    gemm_bias<<<gg, 256>>>(query, Wq, bq, qbuf);
    gemm_bias<<<gg, 256>>>(key,   Wk, bk, kbuf);
    gemm_bias<<<gg, 256>>>(value, Wv, bv, vbuf);

    dim3 gs(S / 128, S / 128, B * H);
    scores_mma<<<gs, 256, SMEM_SCORES>>>(qbuf, kbuf, mask, isog, Worg, borg, att);

    softmax_kernel<<<B * H * S, 256>>>(att);

    dim3 ga(S / 128, B * H);
    av_mma<<<ga, 256, SMEM_AV>>>(att, vbuf, cbuf);

    gemm_bias<<<gg, 256>>>(cbuf, Wo, bo, out);
}

// round 4
// speedup vs baseline: 1.5511x; 1.1855x over previous
#include <cuda_runtime.h>
#include <cstdint>

namespace {
constexpr int B = 4, S = 2048, D = 512, H = 8, DK = 64;
}

// Scratch (allocation-free rule: __device__ globals)
__device__ float g_Q[(size_t)B * S * D];
__device__ float g_K[(size_t)B * S * D];
__device__ float g_V[(size_t)B * S * D];
__device__ float g_C[(size_t)B * S * D];
__device__ float g_att[(size_t)B * H * S * S];

// ============================================================================
// Warp-level tf32 MMA helpers (portable PTX — works on compute_103)
// ============================================================================
__device__ __forceinline__ uint32_t f2tf32(float x) {
    uint32_t u;
    asm("cvt.rna.tf32.f32 %0, %1;" : "=r"(u) : "f"(x));
    return u;
}
__device__ __forceinline__ void split_tf32(float x, uint32_t& hi, uint32_t& lo) {
    hi = f2tf32(x);
    lo = f2tf32(x - __uint_as_float(hi));
}
__device__ __forceinline__ void mma_tf32(float c[4], const uint32_t a[4], const uint32_t b[2]) {
    asm volatile(
        "mma.sync.aligned.m16n8k8.row.col.f32.tf32.tf32.f32 "
        "{%0,%1,%2,%3}, {%4,%5,%6,%7}, {%8,%9}, {%0,%1,%2,%3};"
        : "+f"(c[0]), "+f"(c[1]), "+f"(c[2]), "+f"(c[3])
        : "r"(a[0]), "r"(a[1]), "r"(a[2]), "r"(a[3]), "r"(b[0]), "r"(b[1]));
}

// ============================================================================
// Projection GEMM via mma.sync tf32 (3xTF32):
//   Y[M,512] = X[M,512] @ W[512,512]^T + bias   (M = 8192)
// CTA: 128(m) x 128(n), 256 thr = 8 warps (2m x 4n), warp 64x32, K-chunk 64.
// ============================================================================
namespace {
constexpr int GM_STRIDE = 68;
constexpr int SMEM_GEMM = 2 * 128 * GM_STRIDE * 4;     // 69,632 bytes
}

__global__ void __launch_bounds__(256) gemm_mma(
    const float* __restrict__ X, const float* __restrict__ W,
    const float* __restrict__ bias, float* __restrict__ Y)
{
    extern __shared__ float sm[];
    float* Xs = sm;                      // [128][68]
    float* Ws = sm + 128 * GM_STRIDE;    // [128][68]

    const int t = threadIdx.x, lane = t & 31, wid = t >> 5;
    const int g = lane >> 2, tig = lane & 3;
    const int wm = wid & 1, wn = wid >> 1;
    const int m0 = blockIdx.y * 128, n0 = blockIdx.x * 128;

    float acc[4][4][4] = {};

    for (int kc = 0; kc < 512; kc += 64) {
#pragma unroll
        for (int i = t; i < 2048; i += 256) {
            const int row = i >> 4, c4 = (i & 15) * 4;
            float4 xv = *reinterpret_cast<const float4*>(&X[(size_t)(m0 + row) * 512 + kc + c4]);
            float4 wv = *reinterpret_cast<const float4*>(&W[(size_t)(n0 + row) * 512 + kc + c4]);
            *reinterpret_cast<float4*>(&Xs[row * GM_STRIDE + c4]) = xv;
            *reinterpret_cast<float4*>(&Ws[row * GM_STRIDE + c4]) = wv;
        }
        __syncthreads();

#pragma unroll
        for (int ks = 0; ks < 8; ks++) {
            const int kk = ks * 8;
            uint32_t ahi[4][4], alo[4][4];
#pragma unroll
            for (int i = 0; i < 4; i++) {
                const int r0 = (wm * 64 + i * 16 + g) * GM_STRIDE;
                const int r1 = r0 + 8 * GM_STRIDE;
                split_tf32(Xs[r0 + kk + tig],     ahi[i][0], alo[i][0]);
                split_tf32(Xs[r1 + kk + tig],     ahi[i][1], alo[i][1]);
                split_tf32(Xs[r0 + kk + tig + 4], ahi[i][2], alo[i][2]);
                split_tf32(Xs[r1 + kk + tig + 4], ahi[i][3], alo[i][3]);
            }
#pragma unroll
            for (int j = 0; j < 4; j++) {
                const int nr = (wn * 32 + j * 8 + g) * GM_STRIDE;
                uint32_t bhi[2], blo[2];
                split_tf32(Ws[nr + kk + tig],     bhi[0], blo[0]);
                split_tf32(Ws[nr + kk + tig + 4], bhi[1], blo[1]);
#pragma unroll
                for (int i = 0; i < 4; i++) {
                    mma_tf32(acc[i][j], ahi[i], bhi);
                    mma_tf32(acc[i][j], alo[i], bhi);
                    mma_tf32(acc[i][j], ahi[i], blo);
                }
            }
        }
        __syncthreads();
    }

#pragma unroll
    for (int i = 0; i < 4; i++) {
        const int row0 = m0 + wm * 64 + i * 16 + g;
#pragma unroll
        for (int j = 0; j < 4; j++) {
            const int col = n0 + wn * 32 + j * 8 + 2 * tig;
            const float b0 = __ldg(bias + col), b1 = __ldg(bias + col + 1);
            float2 o;
            o.x = acc[i][j][0] + b0; o.y = acc[i][j][1] + b1;
            *reinterpret_cast<float2*>(&Y[(size_t)row0 * 512 + col]) = o;
            o.x = acc[i][j][2] + b0; o.y = acc[i][j][3] + b1;
            *reinterpret_cast<float2*>(&Y[(size_t)(row0 + 8) * 512 + col]) = o;
        }
    }
}

// ============================================================================
// Scores via mma.sync tf32 (3xTF32): att[bh,q,k] = (Q.K)/8 + organic, masked
// ============================================================================
namespace {
constexpr int SC_STRIDE = 68;
constexpr int SC_QS = 0;
constexpr int SC_KS = 128 * SC_STRIDE;
constexpr int SMEM_SCORES = 2 * 128 * SC_STRIDE * 4;   // 69,632 bytes
}

__global__ void __launch_bounds__(256) scores_mma(
    const float* __restrict__ Q, const float* __restrict__ K,
    const int* __restrict__ mask, const float* __restrict__ is_org,
    const float* __restrict__ Worg, const float* __restrict__ borg,
    float* __restrict__ att)
{
    extern __shared__ float sm[];
    float* Qs = sm + SC_QS;
    float* Ks = sm + SC_KS;

    const int t = threadIdx.x, lane = t & 31, wid = t >> 5;
    const int g = lane >> 2, tig = lane & 3;
    const int wm = wid & 1, wn = wid >> 1;
    const int bh = blockIdx.z, b = bh >> 3, h = bh & 7;
    const int q0 = blockIdx.y * 128, k0g = blockIdx.x * 128;

    const float* Qg = Q + ((size_t)(b * S + q0)) * D + h * DK;
    const float* Kg = K + ((size_t)(b * S + k0g)) * D + h * DK;

#pragma unroll
    for (int i = t; i < 2048; i += 256) {
        const int row = i >> 4, c4 = (i & 15) * 4;
        float4 qv = *reinterpret_cast<const float4*>(Qg + (size_t)row * D + c4);
        float4 kv = *reinterpret_cast<const float4*>(Kg + (size_t)row * D + c4);
        *reinterpret_cast<float4*>(&Qs[row * SC_STRIDE + c4]) = qv;
        *reinterpret_cast<float4*>(&Ks[row * SC_STRIDE + c4]) = kv;
    }
    __syncthreads();

    float acc[4][4][4] = {};

#pragma unroll
    for (int ks = 0; ks < 8; ks++) {
        const int kk = ks * 8;
        uint32_t ahi[4][4], alo[4][4];
#pragma unroll
        for (int i = 0; i < 4; i++) {
            const int r0 = (wm * 64 + i * 16 + g) * SC_STRIDE;
            const int r1 = r0 + 8 * SC_STRIDE;
            split_tf32(Qs[r0 + kk + tig],     ahi[i][0], alo[i][0]);
            split_tf32(Qs[r1 + kk + tig],     ahi[i][1], alo[i][1]);
            split_tf32(Qs[r0 + kk + tig + 4], ahi[i][2], alo[i][2]);
            split_tf32(Qs[r1 + kk + tig + 4], ahi[i][3], alo[i][3]);
        }
#pragma unroll
        for (int j = 0; j < 4; j++) {
            const int nr = (wn * 32 + j * 8 + g) * SC_STRIDE;
            uint32_t bhi[2], blo[2];
            split_tf32(Ks[nr + kk + tig],     bhi[0], blo[0]);
            split_tf32(Ks[nr + kk + tig + 4], bhi[1], blo[1]);
#pragma unroll
            for (int i = 0; i < 4; i++) {
                mma_tf32(acc[i][j], ahi[i], bhi);
                mma_tf32(acc[i][j], alo[i], bhi);
                mma_tf32(acc[i][j], ahi[i], blo);
            }
        }
    }

    const float worg = __ldg(Worg + h), bog = __ldg(borg + h);
    float og[4][2];
#pragma unroll
    for (int i = 0; i < 4; i++) {
#pragma unroll
        for (int hh = 0; hh < 2; hh++) {
            const int row = q0 + wm * 64 + i * 16 + g + hh * 8;
            og[i][hh] = __ldg(is_org + b * S + row) * worg + bog;
        }
    }
    int2 mj[4];
#pragma unroll
    for (int j = 0; j < 4; j++) {
        const int col = k0g + wn * 32 + j * 8 + 2 * tig;
        mj[j] = *reinterpret_cast<const int2*>(mask + b * S + col);
    }

#pragma unroll
    for (int i = 0; i < 4; i++) {
        const int row0 = q0 + wm * 64 + i * 16 + g;
#pragma unroll
        for (int j = 0; j < 4; j++) {
            const int col = k0g + wn * 32 + j * 8 + 2 * tig;
            float2 o;
            float v;
            v = acc[i][j][0] * 0.125f + og[i][0]; o.x = mj[j].x ? v : -1e9f;
            v = acc[i][j][1] * 0.125f + og[i][0]; o.y = mj[j].y ? v : -1e9f;
            *reinterpret_cast<float2*>(&att[((size_t)bh * S + row0) * S + col]) = o;
            v = acc[i][j][2] * 0.125f + og[i][1]; o.x = mj[j].x ? v : -1e9f;
            v = acc[i][j][3] * 0.125f + og[i][1]; o.y = mj[j].y ? v : -1e9f;
            *reinterpret_cast<float2*>(&att[((size_t)bh * S + row0 + 8) * S + col]) = o;
        }
    }
}

// ============================================================================
// AV via mma.sync tf32 (3xTF32)
// ============================================================================
namespace {
constexpr int AV_STRIDE = 68;
constexpr int AV_AS = 0;
constexpr int AV_VS = 128 * AV_STRIDE;
constexpr int SMEM_AV = (128 + 64) * AV_STRIDE * 4;    // 52,224 bytes
}

__global__ void __launch_bounds__(256) av_mma(
    const float* __restrict__ att, const float* __restrict__ V,
    float* __restrict__ C)
{
    extern __shared__ float sm[];
    float* As = sm + AV_AS;   // [128][68]
    float* Vs = sm + AV_VS;   // [64][68]  (Vs[d][k])

    const int t = threadIdx.x, lane = t & 31, wid = t >> 5;
    const int g = lane >> 2, tig = lane & 3;
    const int wm = wid & 3, wn = wid >> 2;
    const int bh = blockIdx.y, b = bh >> 3, h = bh & 7;
    const int q0 = blockIdx.x * 128;

    float acc[2][4][4] = {};

    for (int kc = 0; kc < S; kc += 64) {
#pragma unroll
        for (int i = t; i < 2048; i += 256) {
            const int row = i >> 4, c4 = (i & 15) * 4;
            float4 av = *reinterpret_cast<const float4*>(
                &att[((size_t)bh * S + q0 + row) * S + kc + c4]);
            *reinterpret_cast<float4*>(&As[row * AV_STRIDE + c4]) = av;
        }
#pragma unroll
        for (int i = t; i < 1024; i += 256) {
            const int k = i & 63, d4 = (i >> 6) * 4;
            float4 vv = *reinterpret_cast<const float4*>(
                &V[(size_t)(b * S + kc + k) * D + h * DK + d4]);
            Vs[(d4 + 0) * AV_STRIDE + k] = vv.x;
            Vs[(d4 + 1) * AV_STRIDE + k] = vv.y;
            Vs[(d4 + 2) * AV_STRIDE + k] = vv.z;
            Vs[(d4 + 3) * AV_STRIDE + k] = vv.w;
        }
        __syncthreads();

#pragma unroll
        for (int ks = 0; ks < 8; ks++) {
            const int kk = ks * 8;
            uint32_t ahi[2][4], alo[2][4];
#pragma unroll
            for (int i = 0; i < 2; i++) {
                const int r0 = (wm * 32 + i * 16 + g) * AV_STRIDE;
                const int r1 = r0 + 8 * AV_STRIDE;
                split_tf32(As[r0 + kk + tig],     ahi[i][0], alo[i][0]);
                split_tf32(As[r1 + kk + tig],     ahi[i][1], alo[i][1]);
                split_tf32(As[r0 + kk + tig + 4], ahi[i][2], alo[i][2]);
                split_tf32(As[r1 + kk + tig + 4], ahi[i][3], alo[i][3]);
            }
#pragma unroll
            for (int j = 0; j < 4; j++) {
                const int nr = (wn * 32 + j * 8 + g) * AV_STRIDE;
                uint32_t bhi[2], blo[2];
                split_tf32(Vs[nr + kk + tig],     bhi[0], blo[0]);
                split_tf32(Vs[nr + kk + tig + 4], bhi[1], blo[1]);
#pragma unroll
                for (int i = 0; i < 2; i++) {
                    mma_tf32(acc[i][j], ahi[i], bhi);
                    mma_tf32(acc[i][j], alo[i], bhi);
                    mma_tf32(acc[i][j], ahi[i], blo);
                }
            }
        }
        __syncthreads();
    }

#pragma unroll
    for (int i = 0; i < 2; i++) {
        const int row0 = q0 + wm * 32 + i * 16 + g;
#pragma unroll
        for (int j = 0; j < 4; j++) {
            const int col = h * DK + wn * 32 + j * 8 + 2 * tig;
            float2 o;
            o.x = acc[i][j][0]; o.y = acc[i][j][1];
            *reinterpret_cast<float2*>(&C[(size_t)(b * S + row0) * D + col]) = o;
            o.x = acc[i][j][2]; o.y = acc[i][j][3];
            *reinterpret_cast<float2*>(&C[(size_t)(b * S + row0 + 8) * D + col]) = o;
        }
    }
}

// ---------------------------------------------------------------------------
// Row softmax, in place
// ---------------------------------------------------------------------------
__global__ void __launch_bounds__(256) softmax_kernel(float* __restrict__ att)
{
    float* p = att + (size_t)blockIdx.x * S;
    const int t = threadIdx.x;
    float4 v0 = reinterpret_cast<const float4*>(p)[t * 2 + 0];
    float4 v1 = reinterpret_cast<const float4*>(p)[t * 2 + 1];

    __shared__ float sred[8];

    float m = fmaxf(fmaxf(fmaxf(v0.x, v0.y), fmaxf(v0.z, v0.w)),
                    fmaxf(fmaxf(v1.x, v1.y), fmaxf(v1.z, v1.w)));
#pragma unroll
    for (int o = 16; o; o >>= 1) m = fmaxf(m, __shfl_xor_sync(0xffffffffu, m, o));
    if ((t & 31) == 0) sred[t >> 5] = m;
    __syncthreads();
    float mm = sred[0];
#pragma unroll
    for (int i = 1; i < 8; i++) mm = fmaxf(mm, sred[i]);
    __syncthreads();

    v0.x = expf(v0.x - mm); v0.y = expf(v0.y - mm);
    v0.z = expf(v0.z - mm); v0.w = expf(v0.w - mm);
    v1.x = expf(v1.x - mm); v1.y = expf(v1.y - mm);
    v1.z = expf(v1.z - mm); v1.w = expf(v1.w - mm);

    float s = v0.x + v0.y + v0.z + v0.w + v1.x + v1.y + v1.z + v1.w;
#pragma unroll
    for (int o = 16; o; o >>= 1) s += __shfl_xor_sync(0xffffffffu, s, o);
    if ((t & 31) == 0) sred[t >> 5] = s;
    __syncthreads();
    float ss = sred[0];
#pragma unroll
    for (int i = 1; i < 8; i++) ss += sred[i];
    const float inv = 1.0f / ss;

    v0.x *= inv; v0.y *= inv; v0.z *= inv; v0.w *= inv;
    v1.x *= inv; v1.y *= inv; v1.z *= inv; v1.w *= inv;
    reinterpret_cast<float4*>(p)[t * 2 + 0] = v0;
    reinterpret_cast<float4*>(p)[t * 2 + 1] = v1;
}

// ---------------------------------------------------------------------------
extern "C" void kernel_launch(void* const* d_in, const int* in_sizes, int n_in,
                              void* d_out, int out_size)
{
    const float* query = (const float*)d_in[0];
    const float* key   = (const float*)d_in[1];
    const float* value = (const float*)d_in[2];
    const int*   mask  = (const int*)d_in[3];
    const float* isog  = (const float*)d_in[4];
    const float* Wq    = (const float*)d_in[5];
    const float* bq    = (const float*)d_in[6];
    const float* Wk    = (const float*)d_in[7];
    const float* bk    = (const float*)d_in[8];
    const float* Wv    = (const float*)d_in[9];
    const float* bv    = (const float*)d_in[10];
    const float* Wo    = (const float*)d_in[11];
    const float* bo    = (const float*)d_in[12];
    const float* Worg  = (const float*)d_in[13];
    const float* borg  = (const float*)d_in[14];

    float* out = (float*)d_out;

    float *qbuf, *kbuf, *vbuf, *cbuf;
    cudaGetSymbolAddress((void**)&qbuf, g_Q);
    cudaGetSymbolAddress((void**)&kbuf, g_K);
    cudaGetSymbolAddress((void**)&vbuf, g_V);
    cudaGetSymbolAddress((void**)&cbuf, g_C);

    const long long OUT_MAIN = (long long)B * S * D;
    const long long ATT_SZ   = (long long)B * H * S * S;
    float* att;
    if ((long long)out_size >= OUT_MAIN + ATT_SZ) {
        att = out + OUT_MAIN;
    } else {
        cudaGetSymbolAddress((void**)&att, g_att);
    }

    static bool attr_done = false;
    if (!attr_done) {
        cudaFuncSetAttribute(scores_mma, cudaFuncAttributeMaxDynamicSharedMemorySize, SMEM_SCORES);
        cudaFuncSetAttribute(av_mma, cudaFuncAttributeMaxDynamicSharedMemorySize, SMEM_AV);
        cudaFuncSetAttribute(gemm_mma, cudaFuncAttributeMaxDynamicSharedMemorySize, SMEM_GEMM);
        attr_done = true;
    }

    dim3 gg(4, 64);   // N/128 x M/128
    gemm_mma<<<gg, 256, SMEM_GEMM>>>(query, Wq, bq, qbuf);
    gemm_mma<<<gg, 256, SMEM_GEMM>>>(key,   Wk, bk, kbuf);
    gemm_mma<<<gg, 256, SMEM_GEMM>>>(value, Wv, bv, vbuf);

    dim3 gs(S / 128, S / 128, B * H);
    scores_mma<<<gs, 256, SMEM_SCORES>>>(qbuf, kbuf, mask, isog, Worg, borg, att);

    softmax_kernel<<<B * H * S, 256>>>(att);

    dim3 ga(S / 128, B * H);
    av_mma<<<ga, 256, SMEM_AV>>>(att, vbuf, cbuf);

    gemm_mma<<<gg, 256, SMEM_GEMM>>>(cbuf, Wo, bo, out);
}